// round 1
// baseline (speedup 1.0000x reference)
#include <cuda_runtime.h>
#include <math.h>
#include <stdint.h>

#define BATCH 2
#define SEQ   2048
#define DIMM  1024
#define HEADS 16
#define DHD   64
#define INNER_ (HEADS*DHD)      // 1024
#define ROWS  (BATCH*SEQ)       // 4096

// Scratch (no cudaMalloc allowed) — device globals.
__device__ float g_q [ROWS*INNER_];   // 16.8 MB  q = x@Wq (unscaled)
__device__ float g_kv[ROWS*2*DHD];    //  2.1 MB  kv = x@Wkv  ([k|v] per row)
__device__ float g_ao[ROWS*INNER_];   // 16.8 MB  attention output (b,n,h*64+d)

// ---------------------------------------------------------------------------
// Generic tiled SGEMM: C[M,N] = A[M,K] @ B[K,N] (+bias), all row-major fp32.
// Requires: M%BM==0, N%BN==0, K%BK==0, NT == BM*BK/4 == BK*BN/4 == (BM/TM)*(BN/TN)
// ---------------------------------------------------------------------------
template<int BM,int BN,int BK,int TM,int TN,int NT>
__global__ __launch_bounds__(NT) void sgemm_kernel(
    const float* __restrict__ A, const float* __restrict__ B,
    float* __restrict__ C, int M, int N, int K, const float* __restrict__ bias)
{
    __shared__ float As[BK][BM];
    __shared__ float Bs[BK][BN];

    const int tid = threadIdx.x;
    const int bx = blockIdx.x, by = blockIdx.y;

    constexpr int AV = BK/4;                 // float4 per A-tile row
    const int arow = tid / AV;
    const int acol = (tid % AV)*4;
    constexpr int BV = BN/4;
    const int brow = tid / BV;
    const int bcol = (tid % BV)*4;
    constexpr int TX = BN/TN;
    const int tx = tid % TX;
    const int ty = tid / TX;

    float acc[TM][TN];
    #pragma unroll
    for (int i = 0; i < TM; i++)
        #pragma unroll
        for (int j = 0; j < TN; j++) acc[i][j] = 0.f;

    const float* Ap = A + (size_t)(by*BM + arow)*K + acol;
    const float* Bp = B + (size_t)brow*N + bx*BN + bcol;

    for (int k0 = 0; k0 < K; k0 += BK) {
        float4 av = *(const float4*)(Ap + k0);
        As[acol+0][arow] = av.x;
        As[acol+1][arow] = av.y;
        As[acol+2][arow] = av.z;
        As[acol+3][arow] = av.w;
        float4 bv = *(const float4*)(Bp + (size_t)k0*N);
        *(float4*)&Bs[brow][bcol] = bv;
        __syncthreads();

        #pragma unroll
        for (int kk = 0; kk < BK; kk++) {
            float ra[TM], rb[TN];
            #pragma unroll
            for (int i = 0; i < TM; i += 4)
                *(float4*)&ra[i] = *(const float4*)&As[kk][ty*TM + i];
            #pragma unroll
            for (int j = 0; j < TN; j += 4)
                *(float4*)&rb[j] = *(const float4*)&Bs[kk][tx*TN + j];
            #pragma unroll
            for (int i = 0; i < TM; i++)
                #pragma unroll
                for (int j = 0; j < TN; j++)
                    acc[i][j] += ra[i]*rb[j];
        }
        __syncthreads();
    }

    #pragma unroll
    for (int i = 0; i < TM; i++) {
        const int row = by*BM + ty*TM + i;
        float* cp = C + (size_t)row*N + bx*BN + tx*TN;
        #pragma unroll
        for (int j = 0; j < TN; j += 4) {
            float4 v;
            v.x = acc[i][j+0]; v.y = acc[i][j+1];
            v.z = acc[i][j+2]; v.w = acc[i][j+3];
            if (bias) {
                const float* bp = bias + bx*BN + tx*TN + j;
                v.x += bp[0]; v.y += bp[1]; v.z += bp[2]; v.w += bp[3];
            }
            *(float4*)(cp + j) = v;
        }
    }
}

// ---------------------------------------------------------------------------
// T5 relative-position bucket, mirroring the jax fp32 math exactly.
// nn = i - j >= 0 (causal side only).
// ---------------------------------------------------------------------------
__device__ __forceinline__ int rel_bucket(int nn) {
    if (nn < 16) return nn;
    // jax: 16 + int32( log(n/16) / log(8) * 16 ), clamped to 31. All fp32.
    float t = logf((float)nn * (1.0f/16.0f)) / 2.0794415416798357f * 16.0f;
    int v = 16 + (int)t;
    return v < 31 ? v : 31;
}

// ---------------------------------------------------------------------------
// Flash attention (causal, MQA, relative-position bias), fp32.
// Grid: (SEQ/64, HEADS, BATCH), 256 threads.
// Thread (ty,tx) owns a 4x4 micro-tile: rows ty*4.., cols tx*4..
// ---------------------------------------------------------------------------
struct FlashSmem {
    float Qs[64][68];
    float Ks[64][68];
    float Vs[64][68];
    float Ps[64][68];
    float m_s[64];
    float l_s[64];
    float sc_s[64];
    float biasv[2048];   // bias[nn] = rel_emb[bucket(nn)][h] * 8
};

__global__ __launch_bounds__(256) void flash_kernel(
    const float* __restrict__ Q,        // [ROWS, 1024] unscaled
    const float* __restrict__ KV,       // [ROWS, 128]  [k|v]
    const float* __restrict__ rel_emb,  // [32, 16]
    float* __restrict__ AO)             // [ROWS, 1024]
{
    extern __shared__ char smem_raw[];
    FlashSmem& sm = *reinterpret_cast<FlashSmem*>(smem_raw);

    const int qt = blockIdx.x, h = blockIdx.y, b = blockIdx.z;
    const int tid = threadIdx.x;
    const int tx = tid & 15, ty = tid >> 4;
    const int i0 = qt * 64;

    // bias lookup table for this head (8 logf per thread, once per block)
    for (int nn = tid; nn < 2048; nn += 256)
        sm.biasv[nn] = rel_emb[rel_bucket(nn)*HEADS + h] * 8.0f;
    if (tid < 64) { sm.m_s[tid] = -INFINITY; sm.l_s[tid] = 0.f; }

    // load Q tile (scaled by dim_head^-0.5 = 0.125)
    {
        const int r  = tid >> 2;
        const int c0 = (tid & 3) * 16;
        const float* qp = Q + (size_t)(b*SEQ + i0 + r)*INNER_ + h*DHD + c0;
        #pragma unroll
        for (int c = 0; c < 4; c++) {
            float4 v = *(const float4*)(qp + c*4);
            v.x *= 0.125f; v.y *= 0.125f; v.z *= 0.125f; v.w *= 0.125f;
            *(float4*)&sm.Qs[r][c0 + c*4] = v;
        }
    }
    __syncthreads();

    float o[4][4];
    #pragma unroll
    for (int i = 0; i < 4; i++)
        #pragma unroll
        for (int j = 0; j < 4; j++) o[i][j] = 0.f;

    for (int jt = 0; jt <= qt; jt++) {
        // load K,V tiles
        {
            const int r  = tid >> 2;
            const int c0 = (tid & 3) * 16;
            const float* kp = KV + (size_t)(b*SEQ + jt*64 + r)*(2*DHD);
            #pragma unroll
            for (int c = 0; c < 4; c++) {
                float4 kv4 = *(const float4*)(kp + c0 + c*4);
                *(float4*)&sm.Ks[r][c0 + c*4] = kv4;
                float4 vv4 = *(const float4*)(kp + DHD + c0 + c*4);
                *(float4*)&sm.Vs[r][c0 + c*4] = vv4;
            }
        }
        __syncthreads();

        // S = Q K^T (64x64x64), 4x4 per thread
        float s[4][4];
        #pragma unroll
        for (int i = 0; i < 4; i++)
            #pragma unroll
            for (int j = 0; j < 4; j++) s[i][j] = 0.f;

        #pragma unroll
        for (int d = 0; d < 64; d += 4) {
            float4 qv[4], kk[4];
            #pragma unroll
            for (int ii = 0; ii < 4; ii++)
                qv[ii] = *(const float4*)&sm.Qs[ty*4 + ii][d];
            #pragma unroll
            for (int jj = 0; jj < 4; jj++)
                kk[jj] = *(const float4*)&sm.Ks[tx*4 + jj][d];
            #pragma unroll
            for (int ii = 0; ii < 4; ii++)
                #pragma unroll
                for (int jj = 0; jj < 4; jj++)
                    s[ii][jj] += qv[ii].x*kk[jj].x + qv[ii].y*kk[jj].y
                               + qv[ii].z*kk[jj].z + qv[ii].w*kk[jj].w;
        }

        // bias + causal mask
        const int j0 = jt * 64;
        #pragma unroll
        for (int ii = 0; ii < 4; ii++) {
            const int i = i0 + ty*4 + ii;
            #pragma unroll
            for (int jj = 0; jj < 4; jj++) {
                const int nn = i - (j0 + tx*4 + jj);
                if (nn < 0) s[ii][jj] = -INFINITY;
                else        s[ii][jj] += sm.biasv[nn];
            }
        }

        // online softmax: row max/sum across the 16-lane row group
        float rmax[4], rsum[4], m_old[4], m_new[4];
        #pragma unroll
        for (int ii = 0; ii < 4; ii++) {
            float mx = fmaxf(fmaxf(s[ii][0], s[ii][1]), fmaxf(s[ii][2], s[ii][3]));
            #pragma unroll
            for (int off = 8; off >= 1; off >>= 1)
                mx = fmaxf(mx, __shfl_xor_sync(0xffffffffu, mx, off, 16));
            rmax[ii] = mx;
            m_old[ii] = sm.m_s[ty*4 + ii];
            m_new[ii] = fmaxf(m_old[ii], mx);
        }
        #pragma unroll
        for (int ii = 0; ii < 4; ii++) {
            float4 p4;
            p4.x = __expf(s[ii][0] - m_new[ii]);
            p4.y = __expf(s[ii][1] - m_new[ii]);
            p4.z = __expf(s[ii][2] - m_new[ii]);
            p4.w = __expf(s[ii][3] - m_new[ii]);
            *(float4*)&sm.Ps[ty*4 + ii][tx*4] = p4;
            float sum = p4.x + p4.y + p4.z + p4.w;
            #pragma unroll
            for (int off = 8; off >= 1; off >>= 1)
                sum += __shfl_xor_sync(0xffffffffu, sum, off, 16);
            rsum[ii] = sum;
        }
        __syncwarp();
        if (tx == 0) {
            #pragma unroll
            for (int ii = 0; ii < 4; ii++) {
                const int i = ty*4 + ii;
                const float sc = __expf(m_old[ii] - m_new[ii]);
                sm.sc_s[i] = sc;
                sm.l_s[i] = sm.l_s[i]*sc + rsum[ii];
                sm.m_s[i] = m_new[ii];
            }
        }
        __syncthreads();

        // O = O*scale + P V  (thread owns rows ty*4.., dims tx*4..)
        float scr[4];
        #pragma unroll
        for (int ii = 0; ii < 4; ii++) scr[ii] = sm.sc_s[ty*4 + ii];
        #pragma unroll
        for (int ii = 0; ii < 4; ii++)
            #pragma unroll
            for (int dd = 0; dd < 4; dd++) o[ii][dd] *= scr[ii];

        #pragma unroll
        for (int j = 0; j < 64; j += 4) {
            float4 pv[4], vv[4];
            #pragma unroll
            for (int ii = 0; ii < 4; ii++)
                pv[ii] = *(const float4*)&sm.Ps[ty*4 + ii][j];
            #pragma unroll
            for (int jj = 0; jj < 4; jj++)
                vv[jj] = *(const float4*)&sm.Vs[j + jj][tx*4];
            #pragma unroll
            for (int ii = 0; ii < 4; ii++) {
                o[ii][0] += pv[ii].x*vv[0].x + pv[ii].y*vv[1].x + pv[ii].z*vv[2].x + pv[ii].w*vv[3].x;
                o[ii][1] += pv[ii].x*vv[0].y + pv[ii].y*vv[1].y + pv[ii].z*vv[2].y + pv[ii].w*vv[3].y;
                o[ii][2] += pv[ii].x*vv[0].z + pv[ii].y*vv[1].z + pv[ii].z*vv[2].z + pv[ii].w*vv[3].z;
                o[ii][3] += pv[ii].x*vv[0].w + pv[ii].y*vv[1].w + pv[ii].z*vv[2].w + pv[ii].w*vv[3].w;
            }
        }
        __syncthreads();
    }

    // normalize + store
    #pragma unroll
    for (int ii = 0; ii < 4; ii++) {
        const float inv = 1.0f / sm.l_s[ty*4 + ii];
        const int row = b*SEQ + i0 + ty*4 + ii;
        float4 v;
        v.x = o[ii][0]*inv; v.y = o[ii][1]*inv;
        v.z = o[ii][2]*inv; v.w = o[ii][3]*inv;
        *(float4*)(AO + (size_t)row*INNER_ + h*DHD + tx*4) = v;
    }
}

// ---------------------------------------------------------------------------
extern "C" void kernel_launch(void* const* d_in, const int* in_sizes, int n_in,
                              void* d_out, int out_size)
{
    const float* x       = (const float*)d_in[0];  // (2,2048,1024)
    const float* Wq      = (const float*)d_in[1];  // (1024,1024)
    const float* Wkv     = (const float*)d_in[2];  // (1024,128)
    const float* Wout    = (const float*)d_in[3];  // (1024,1024)
    const float* bout    = (const float*)d_in[4];  // (1024,)
    const float* rel_emb = (const float*)d_in[5];  // (32,16)
    float* out = (float*)d_out;

    void *qp_, *kvp_, *aop_;
    cudaGetSymbolAddress(&qp_,  g_q);
    cudaGetSymbolAddress(&kvp_, g_kv);
    cudaGetSymbolAddress(&aop_, g_ao);
    float* qp  = (float*)qp_;
    float* kvp = (float*)kvp_;
    float* aop = (float*)aop_;

    cudaFuncSetAttribute(flash_kernel,
                         cudaFuncAttributeMaxDynamicSharedMemorySize,
                         (int)sizeof(FlashSmem));

    // q = x @ Wq    (4096x1024x1024)
    {
        dim3 g(INNER_/128, ROWS/128);
        sgemm_kernel<128,128,8,8,8,256><<<g, 256>>>(x, Wq, qp, ROWS, INNER_, DIMM, nullptr);
    }
    // kv = x @ Wkv  (4096x128x1024) — smaller tiles so the grid fills the chip
    {
        dim3 g((2*DHD)/64, ROWS/64);
        sgemm_kernel<64,64,16,4,4,256><<<g, 256>>>(x, Wkv, kvp, ROWS, 2*DHD, DIMM, nullptr);
    }
    // attention
    {
        dim3 g(SEQ/64, HEADS, BATCH);
        flash_kernel<<<g, 256, sizeof(FlashSmem)>>>(qp, kvp, rel_emb, aop);
    }
    // out = ao @ Wout + bout
    {
        dim3 g(DIMM/128, ROWS/128);
        sgemm_kernel<128,128,8,8,8,256><<<g, 256>>>(aop, Wout, out, ROWS, DIMM, INNER_, bout);
    }
}

// round 4
// speedup vs baseline: 2.3305x; 2.3305x over previous
#include <cuda_runtime.h>
#include <cuda_bf16.h>
#include <math.h>
#include <stdint.h>

#define BATCH 2
#define SEQ   2048
#define DIMM  1024
#define HEADS 16
#define DHD   64
#define INNER_ (HEADS*DHD)      // 1024
#define ROWS  (BATCH*SEQ)       // 4096
#define KDIM  1024

// ---------------- scratch (no cudaMalloc allowed) ----------------
__device__ __align__(256) float g_q [ROWS*INNER_];
__device__ __align__(256) float g_kv[ROWS*2*DHD];
__device__ __align__(256) float g_ao[ROWS*INNER_];
__device__ __align__(256) __nv_bfloat16 g_xh [ROWS*DIMM];
__device__ __align__(256) __nv_bfloat16 g_xl [ROWS*DIMM];
__device__ __align__(256) __nv_bfloat16 g_aoh[ROWS*INNER_];
__device__ __align__(256) __nv_bfloat16 g_aol[ROWS*INNER_];
__device__ __align__(256) __nv_bfloat16 g_wqt_h [INNER_*DIMM];
__device__ __align__(256) __nv_bfloat16 g_wqt_l [INNER_*DIMM];
__device__ __align__(256) __nv_bfloat16 g_wkvt_h[2*DHD*DIMM];
__device__ __align__(256) __nv_bfloat16 g_wkvt_l[2*DHD*DIMM];
__device__ __align__(256) __nv_bfloat16 g_wot_h [DIMM*INNER_];
__device__ __align__(256) __nv_bfloat16 g_wot_l [DIMM*INNER_];

// ---------------- helpers ----------------
__device__ __forceinline__ uint32_t s2u(const void* p) {
    uint32_t a;
    asm("{ .reg .u64 t; cvta.to.shared.u64 t, %1; cvt.u32.u64 %0, t; }"
        : "=r"(a) : "l"(p));
    return a;
}
__device__ __forceinline__ void cp16(uint32_t dst, const void* src) {
    asm volatile("cp.async.cg.shared.global [%0], [%1], 16;" :: "r"(dst), "l"(src));
}
__device__ __forceinline__ void cp_commit() { asm volatile("cp.async.commit_group;" ::: "memory"); }

// HMMA m16n8k16, bf16 inputs, fp32 accumulate. Legal at compute_103 (sm_80+).
__device__ __forceinline__ void mma16816(float c[4], const uint32_t a[4], const uint32_t b[2]) {
    asm volatile("mma.sync.aligned.m16n8k16.row.col.f32.bf16.bf16.f32 "
        "{%0,%1,%2,%3}, {%4,%5,%6,%7}, {%8,%9}, {%0,%1,%2,%3};"
        : "+f"(c[0]), "+f"(c[1]), "+f"(c[2]), "+f"(c[3])
        : "r"(a[0]), "r"(a[1]), "r"(a[2]), "r"(a[3]), "r"(b[0]), "r"(b[1]));
}

// Fragment loads from padded row-major smem (stride in elements).
// l4 = lane>>2, c2 = (lane&3)*2 must be in scope.
#define LDA_FR(fr, arr, row0, kcol, STRIDE) do { \
    (fr)[0] = *(const uint32_t*)&(arr)[((row0) + l4    )*(STRIDE) + (kcol) + c2    ]; \
    (fr)[1] = *(const uint32_t*)&(arr)[((row0) + l4 + 8)*(STRIDE) + (kcol) + c2    ]; \
    (fr)[2] = *(const uint32_t*)&(arr)[((row0) + l4    )*(STRIDE) + (kcol) + c2 + 8]; \
    (fr)[3] = *(const uint32_t*)&(arr)[((row0) + l4 + 8)*(STRIDE) + (kcol) + c2 + 8]; \
} while(0)
#define LDB_FR(fr, arr, n0, kcol, STRIDE) do { \
    (fr)[0] = *(const uint32_t*)&(arr)[((n0) + l4)*(STRIDE) + (kcol) + c2    ]; \
    (fr)[1] = *(const uint32_t*)&(arr)[((n0) + l4)*(STRIDE) + (kcol) + c2 + 8]; \
} while(0)

// ---------------------------------------------------------------------------
// Prep kernels
// ---------------------------------------------------------------------------
__global__ __launch_bounds__(256) void split_kernel(
    const float* __restrict__ A, __nv_bfloat16* __restrict__ H,
    __nv_bfloat16* __restrict__ L, int n4)
{
    int i = blockIdx.x * blockDim.x + threadIdx.x;
    if (i >= n4) return;
    float4 a = ((const float4*)A)[i];
    __nv_bfloat16 h0 = __float2bfloat16(a.x), h1 = __float2bfloat16(a.y);
    __nv_bfloat16 h2 = __float2bfloat16(a.z), h3 = __float2bfloat16(a.w);
    __nv_bfloat16 l0 = __float2bfloat16(a.x - __bfloat162float(h0));
    __nv_bfloat16 l1 = __float2bfloat16(a.y - __bfloat162float(h1));
    __nv_bfloat16 l2 = __float2bfloat16(a.z - __bfloat162float(h2));
    __nv_bfloat16 l3 = __float2bfloat16(a.w - __bfloat162float(h3));
    ((__nv_bfloat162*)H)[2*i]   = __halves2bfloat162(h0, h1);
    ((__nv_bfloat162*)H)[2*i+1] = __halves2bfloat162(h2, h3);
    ((__nv_bfloat162*)L)[2*i]   = __halves2bfloat162(l0, l1);
    ((__nv_bfloat162*)L)[2*i+1] = __halves2bfloat162(l2, l3);
}

__global__ __launch_bounds__(256) void transpose_split_kernel(
    const float* __restrict__ W, __nv_bfloat16* __restrict__ TH,
    __nv_bfloat16* __restrict__ TL, int K, int N)
{
    __shared__ float tile[32][33];
    const int tx = threadIdx.x, ty = threadIdx.y;     // block (32,8)
    const int n0 = blockIdx.x * 32, k0 = blockIdx.y * 32;
    #pragma unroll
    for (int i = 0; i < 4; i++)
        tile[ty + 8*i][tx] = W[(size_t)(k0 + ty + 8*i) * N + n0 + tx];
    __syncthreads();
    #pragma unroll
    for (int i = 0; i < 4; i++) {
        float a = tile[tx][ty + 8*i];
        __nv_bfloat16 h = __float2bfloat16(a);
        __nv_bfloat16 l = __float2bfloat16(a - __bfloat162float(h));
        size_t o = (size_t)(n0 + ty + 8*i) * K + k0 + tx;
        TH[o] = h; TL[o] = l;
    }
}

// ---------------------------------------------------------------------------
// HMMA GEMM: C[M,N] = (Ah+Al)[M,K] @ (Bh+Bl)^T, B stored [N][K] K-major bf16.
// CTA 128x128, BK=32, 2-stage cp.async. 8 warps, each 32x64.
// ---------------------------------------------------------------------------
#define GBK 32
#define GNSTG (KDIM/GBK)           // 32
#define GSTRIDE 40                 // padded row stride (elements)
#define GMATB (128*GSTRIDE*2)      // 10240 bytes per matrix
#define GSTGB (4*GMATB)            // 40960 bytes per stage
#define GEMM_SMEM (2*GSTGB)

__global__ __launch_bounds__(256) void gemm_mma(
    const __nv_bfloat16* __restrict__ Ah, const __nv_bfloat16* __restrict__ Al,
    const __nv_bfloat16* __restrict__ Bh, const __nv_bfloat16* __restrict__ Bl,
    float* __restrict__ C, int N, const float* __restrict__ bias)
{
    extern __shared__ __align__(16) char smem[];
    const uint32_t sbuf = s2u(smem);
    const int tid = threadIdx.x, wid = tid >> 5, lane = tid & 31;
    const int l4 = lane >> 2, c2 = (lane & 3) * 2;
    const int wm = wid & 3, wn = wid >> 2;
    const int bn = blockIdx.x, bm = blockIdx.y;

    const __nv_bfloat16* pA[2] = { Ah + (size_t)(bm*128)*KDIM, Al + (size_t)(bm*128)*KDIM };
    const __nv_bfloat16* pB[2] = { Bh + (size_t)(bn*128)*KDIM, Bl + (size_t)(bn*128)*KDIM };

    const int r0 = tid >> 2, kc = tid & 3;   // chunk 0: rows 0..63
    const int r1 = r0 + 64;                  // chunk 1: rows 64..127

    float acc[2][8][4];
    #pragma unroll
    for (int i = 0; i < 2; i++)
        #pragma unroll
        for (int j = 0; j < 8; j++)
            #pragma unroll
            for (int e = 0; e < 4; e++) acc[i][j][e] = 0.f;

    #define G_LOAD(S) do { \
        const int _k0 = (S) * GBK; \
        const uint32_t stb = sbuf + ((S) & 1) * GSTGB; \
        _Pragma("unroll") \
        for (int m = 0; m < 2; m++) { \
            cp16(stb + m*GMATB           + r0*80 + kc*16, pA[m] + (size_t)r0*KDIM + _k0 + kc*8); \
            cp16(stb + m*GMATB           + r1*80 + kc*16, pA[m] + (size_t)r1*KDIM + _k0 + kc*8); \
            cp16(stb + (m+2)*GMATB       + r0*80 + kc*16, pB[m] + (size_t)r0*KDIM + _k0 + kc*8); \
            cp16(stb + (m+2)*GMATB       + r1*80 + kc*16, pB[m] + (size_t)r1*KDIM + _k0 + kc*8); \
        } \
    } while (0)

    G_LOAD(0); cp_commit();

    for (int s = 0; s < GNSTG; s++) {
        if (s + 1 < GNSTG) {
            G_LOAD(s + 1); cp_commit();
            asm volatile("cp.async.wait_group 1;" ::: "memory");
        } else {
            asm volatile("cp.async.wait_group 0;" ::: "memory");
        }
        __syncthreads();

        const __nv_bfloat16* base = (const __nv_bfloat16*)(smem + (s & 1) * GSTGB);
        const __nv_bfloat16* As_h = base;
        const __nv_bfloat16* As_l = base + 128*GSTRIDE;
        const __nv_bfloat16* Bs_h = base + 2*128*GSTRIDE;
        const __nv_bfloat16* Bs_l = base + 3*128*GSTRIDE;
        const int arow = wm*32, bcol = wn*64;

        #pragma unroll
        for (int k16 = 0; k16 < 2; k16++) {
            const int kcol = k16 * 16;
            uint32_t af[2][4], bf_[8][2];
            // Ah x Bh
            #pragma unroll
            for (int mt = 0; mt < 2; mt++) LDA_FR(af[mt], As_h, arow + mt*16, kcol, GSTRIDE);
            #pragma unroll
            for (int nt = 0; nt < 8; nt++) LDB_FR(bf_[nt], Bs_h, bcol + nt*8, kcol, GSTRIDE);
            #pragma unroll
            for (int mt = 0; mt < 2; mt++)
                #pragma unroll
                for (int nt = 0; nt < 8; nt++) mma16816(acc[mt][nt], af[mt], bf_[nt]);
            // Ah x Bl
            #pragma unroll
            for (int nt = 0; nt < 8; nt++) LDB_FR(bf_[nt], Bs_l, bcol + nt*8, kcol, GSTRIDE);
            #pragma unroll
            for (int mt = 0; mt < 2; mt++)
                #pragma unroll
                for (int nt = 0; nt < 8; nt++) mma16816(acc[mt][nt], af[mt], bf_[nt]);
            // Al x Bh
            #pragma unroll
            for (int mt = 0; mt < 2; mt++) LDA_FR(af[mt], As_l, arow + mt*16, kcol, GSTRIDE);
            #pragma unroll
            for (int nt = 0; nt < 8; nt++) LDB_FR(bf_[nt], Bs_h, bcol + nt*8, kcol, GSTRIDE);
            #pragma unroll
            for (int mt = 0; mt < 2; mt++)
                #pragma unroll
                for (int nt = 0; nt < 8; nt++) mma16816(acc[mt][nt], af[mt], bf_[nt]);
        }
        __syncthreads();
    }
    #undef G_LOAD

    // epilogue
    #pragma unroll
    for (int mt = 0; mt < 2; mt++) {
        const int rg0 = bm*128 + wm*32 + mt*16 + l4;
        #pragma unroll
        for (int nt = 0; nt < 8; nt++) {
            const int cg = bn*128 + wn*64 + nt*8 + c2;
            float b0 = 0.f, b1 = 0.f;
            if (bias) { b0 = bias[cg]; b1 = bias[cg+1]; }
            float2 v0 = { acc[mt][nt][0] + b0, acc[mt][nt][1] + b1 };
            float2 v1 = { acc[mt][nt][2] + b0, acc[mt][nt][3] + b1 };
            *(float2*)(C + (size_t)rg0*N + cg)       = v0;
            *(float2*)(C + (size_t)(rg0+8)*N + cg)   = v1;
        }
    }
}

// ---------------------------------------------------------------------------
// T5 relative-position bucket (mirrors jax fp32 math)
// ---------------------------------------------------------------------------
__device__ __forceinline__ int rel_bucket(int nn) {
    if (nn < 16) return nn;
    float t = logf((float)nn * (1.0f/16.0f)) / 2.0794415416798357f * 16.0f;
    int v = 16 + (int)t;
    return v < 31 ? v : 31;
}

// ---------------------------------------------------------------------------
// Flash attention with HMMA (causal, MQA, rel-pos bias).
// Grid (SEQ/64, HEADS, BATCH), 256 threads = 8 warps.
// ---------------------------------------------------------------------------
#define FST 72   // bf16 smem row stride
struct FSmem {
    __nv_bfloat16 Qh[64][FST], Ql[64][FST];
    __nv_bfloat16 Kh[64][FST], Kl[64][FST];
    __nv_bfloat16 Vth[64][FST], Vtl[64][FST];   // transposed V: [d][j]
    __nv_bfloat16 Ph[64][FST], Pl[64][FST];
    float Ps[64][68];
    float biasv[2048];
    float m_s[64], l_s[64], sc_s[64];
};

__global__ __launch_bounds__(256) void flash_mma(
    const float* __restrict__ Q, const float* __restrict__ KV,
    const float* __restrict__ rel_emb, float* __restrict__ AO)
{
    extern __shared__ __align__(16) char smem_raw[];
    FSmem& sm = *reinterpret_cast<FSmem*>(smem_raw);

    const int qt = blockIdx.x, h = blockIdx.y, b = blockIdx.z;
    const int tid = threadIdx.x;
    const int lane = tid & 31;
    const int l4 = lane >> 2, c2 = (lane & 3) * 2;
    const int wid = tid >> 5;
    const int wm = wid & 3, wn = wid >> 2;
    const int mrow0 = wm * 16, ncol0 = wn * 32;
    const int tx = tid & 15, ty = tid >> 4;
    const int i0 = qt * 64;

    // bias table + state init
    for (int nn = tid; nn < 2048; nn += 256)
        sm.biasv[nn] = rel_emb[rel_bucket(nn)*HEADS + h] * 8.0f;
    if (tid < 64) { sm.m_s[tid] = -INFINITY; sm.l_s[tid] = 0.f; }

    // Q load + scale + bf16 split
    {
        const int r  = tid >> 2;
        const int c0 = (tid & 3) * 16;
        const float* qp = Q + (size_t)(b*SEQ + i0 + r)*INNER_ + h*DHD + c0;
        #pragma unroll
        for (int c = 0; c < 4; c++) {
            float4 v = *(const float4*)(qp + c*4);
            float vv[4] = { v.x*0.125f, v.y*0.125f, v.z*0.125f, v.w*0.125f };
            #pragma unroll
            for (int e = 0; e < 4; e++) {
                __nv_bfloat16 hi = __float2bfloat16(vv[e]);
                sm.Qh[r][c0 + c*4 + e] = hi;
                sm.Ql[r][c0 + c*4 + e] = __float2bfloat16(vv[e] - __bfloat162float(hi));
            }
        }
    }

    float o[4][4];
    #pragma unroll
    for (int i = 0; i < 4; i++)
        #pragma unroll
        for (int j = 0; j < 4; j++) o[i][j] = 0.f;

    for (int jt = 0; jt <= qt; jt++) {
        __syncthreads();   // protect K/V/bias/Q from previous-iter readers
        // K/V load + split (+V transpose)
        {
            const int r  = tid >> 2;
            const int c0 = (tid & 3) * 16;
            const float* kp = KV + (size_t)(b*SEQ + jt*64 + r)*(2*DHD);
            #pragma unroll
            for (int c = 0; c < 4; c++) {
                float4 kv4 = *(const float4*)(kp + c0 + c*4);
                float kvv[4] = { kv4.x, kv4.y, kv4.z, kv4.w };
                #pragma unroll
                for (int e = 0; e < 4; e++) {
                    __nv_bfloat16 hi = __float2bfloat16(kvv[e]);
                    sm.Kh[r][c0 + c*4 + e] = hi;
                    sm.Kl[r][c0 + c*4 + e] = __float2bfloat16(kvv[e] - __bfloat162float(hi));
                }
                float4 vv4 = *(const float4*)(kp + DHD + c0 + c*4);
                float vvv[4] = { vv4.x, vv4.y, vv4.z, vv4.w };
                #pragma unroll
                for (int e = 0; e < 4; e++) {
                    __nv_bfloat16 hi = __float2bfloat16(vvv[e]);
                    sm.Vth[c0 + c*4 + e][r] = hi;
                    sm.Vtl[c0 + c*4 + e][r] = __float2bfloat16(vvv[e] - __bfloat162float(hi));
                }
            }
        }
        __syncthreads();

        // ---- S = Q K^T via HMMA ----
        float s[4][4];
        #pragma unroll
        for (int nt = 0; nt < 4; nt++)
            #pragma unroll
            for (int e = 0; e < 4; e++) s[nt][e] = 0.f;

        #pragma unroll
        for (int k16 = 0; k16 < 4; k16++) {
            const int kcol = k16 * 16;
            uint32_t af[4], bf_[4][2];
            LDA_FR(af, &sm.Qh[0][0], mrow0, kcol, FST);
            #pragma unroll
            for (int nt = 0; nt < 4; nt++) LDB_FR(bf_[nt], &sm.Kh[0][0], ncol0 + nt*8, kcol, FST);
            #pragma unroll
            for (int nt = 0; nt < 4; nt++) mma16816(s[nt], af, bf_[nt]);
            #pragma unroll
            for (int nt = 0; nt < 4; nt++) LDB_FR(bf_[nt], &sm.Kl[0][0], ncol0 + nt*8, kcol, FST);
            #pragma unroll
            for (int nt = 0; nt < 4; nt++) mma16816(s[nt], af, bf_[nt]);
            LDA_FR(af, &sm.Ql[0][0], mrow0, kcol, FST);
            #pragma unroll
            for (int nt = 0; nt < 4; nt++) LDB_FR(bf_[nt], &sm.Kh[0][0], ncol0 + nt*8, kcol, FST);
            #pragma unroll
            for (int nt = 0; nt < 4; nt++) mma16816(s[nt], af, bf_[nt]);
        }

        // bias + mask + store to Ps
        const int j0 = jt * 64;
        #pragma unroll
        for (int nt = 0; nt < 4; nt++) {
            #pragma unroll
            for (int e = 0; e < 4; e++) {
                const int row = mrow0 + l4 + ((e >> 1) << 3);
                const int col = ncol0 + nt*8 + c2 + (e & 1);
                const int nn = (i0 + row) - (j0 + col);
                float v = s[nt][e];
                sm.Ps[row][col] = (nn < 0) ? -INFINITY : v + sm.biasv[nn];
            }
        }
        __syncthreads();

        // ---- softmax on Ps ----
        {
            float sv[4][4];
            float rsum[4], m_old[4], m_new[4];
            #pragma unroll
            for (int ii = 0; ii < 4; ii++) {
                float4 v = *(const float4*)&sm.Ps[ty*4 + ii][tx*4];
                sv[ii][0] = v.x; sv[ii][1] = v.y; sv[ii][2] = v.z; sv[ii][3] = v.w;
                float mx = fmaxf(fmaxf(v.x, v.y), fmaxf(v.z, v.w));
                #pragma unroll
                for (int off = 8; off >= 1; off >>= 1)
                    mx = fmaxf(mx, __shfl_xor_sync(0xffffffffu, mx, off, 16));
                m_old[ii] = sm.m_s[ty*4 + ii];
                m_new[ii] = fmaxf(m_old[ii], mx);
            }
            #pragma unroll
            for (int ii = 0; ii < 4; ii++) {
                float p0 = __expf(sv[ii][0] - m_new[ii]);
                float p1 = __expf(sv[ii][1] - m_new[ii]);
                float p2 = __expf(sv[ii][2] - m_new[ii]);
                float p3 = __expf(sv[ii][3] - m_new[ii]);
                __nv_bfloat16 h0 = __float2bfloat16(p0), h1 = __float2bfloat16(p1);
                __nv_bfloat16 h2 = __float2bfloat16(p2), h3 = __float2bfloat16(p3);
                *(__nv_bfloat162*)&sm.Ph[ty*4 + ii][tx*4]     = __halves2bfloat162(h0, h1);
                *(__nv_bfloat162*)&sm.Ph[ty*4 + ii][tx*4 + 2] = __halves2bfloat162(h2, h3);
                __nv_bfloat16 q0 = __float2bfloat16(p0 - __bfloat162float(h0));
                __nv_bfloat16 q1 = __float2bfloat16(p1 - __bfloat162float(h1));
                __nv_bfloat16 q2 = __float2bfloat16(p2 - __bfloat162float(h2));
                __nv_bfloat16 q3 = __float2bfloat16(p3 - __bfloat162float(h3));
                *(__nv_bfloat162*)&sm.Pl[ty*4 + ii][tx*4]     = __halves2bfloat162(q0, q1);
                *(__nv_bfloat162*)&sm.Pl[ty*4 + ii][tx*4 + 2] = __halves2bfloat162(q2, q3);
                float sum = p0 + p1 + p2 + p3;
                #pragma unroll
                for (int off = 8; off >= 1; off >>= 1)
                    sum += __shfl_xor_sync(0xffffffffu, sum, off, 16);
                rsum[ii] = sum;
            }
            __syncwarp();
            if (tx == 0) {
                #pragma unroll
                for (int ii = 0; ii < 4; ii++) {
                    const int i = ty*4 + ii;
                    const float sc = __expf(m_old[ii] - m_new[ii]);
                    sm.sc_s[i] = sc;
                    sm.l_s[i] = sm.l_s[i]*sc + rsum[ii];
                    sm.m_s[i] = m_new[ii];
                }
            }
        }
        __syncthreads();

        // ---- O = O*sc + P V via HMMA ----
        {
            const float sc0 = sm.sc_s[mrow0 + l4];
            const float sc1 = sm.sc_s[mrow0 + l4 + 8];
            #pragma unroll
            for (int nt = 0; nt < 4; nt++) {
                o[nt][0] *= sc0; o[nt][1] *= sc0;
                o[nt][2] *= sc1; o[nt][3] *= sc1;
            }
            #pragma unroll
            for (int k16 = 0; k16 < 4; k16++) {
                const int kcol = k16 * 16;
                uint32_t af[4], bf_[4][2];
                LDA_FR(af, &sm.Ph[0][0], mrow0, kcol, FST);
                #pragma unroll
                for (int nt = 0; nt < 4; nt++) LDB_FR(bf_[nt], &sm.Vth[0][0], ncol0 + nt*8, kcol, FST);
                #pragma unroll
                for (int nt = 0; nt < 4; nt++) mma16816(o[nt], af, bf_[nt]);
                #pragma unroll
                for (int nt = 0; nt < 4; nt++) LDB_FR(bf_[nt], &sm.Vtl[0][0], ncol0 + nt*8, kcol, FST);
                #pragma unroll
                for (int nt = 0; nt < 4; nt++) mma16816(o[nt], af, bf_[nt]);
                LDA_FR(af, &sm.Pl[0][0], mrow0, kcol, FST);
                #pragma unroll
                for (int nt = 0; nt < 4; nt++) LDB_FR(bf_[nt], &sm.Vth[0][0], ncol0 + nt*8, kcol, FST);
                #pragma unroll
                for (int nt = 0; nt < 4; nt++) mma16816(o[nt], af, bf_[nt]);
            }
        }
    }
    __syncthreads();

    // normalize + store
    {
        const float inv0 = 1.0f / sm.l_s[mrow0 + l4];
        const float inv1 = 1.0f / sm.l_s[mrow0 + l4 + 8];
        const int rg0 = b*SEQ + i0 + mrow0 + l4;
        #pragma unroll
        for (int nt = 0; nt < 4; nt++) {
            const int dcol = h*DHD + ncol0 + nt*8 + c2;
            float2 v0 = { o[nt][0]*inv0, o[nt][1]*inv0 };
            float2 v1 = { o[nt][2]*inv1, o[nt][3]*inv1 };
            *(float2*)(AO + (size_t)rg0*INNER_ + dcol)       = v0;
            *(float2*)(AO + (size_t)(rg0+8)*INNER_ + dcol)   = v1;
        }
    }
}

// ---------------------------------------------------------------------------
extern "C" void kernel_launch(void* const* d_in, const int* in_sizes, int n_in,
                              void* d_out, int out_size)
{
    const float* x       = (const float*)d_in[0];
    const float* Wq      = (const float*)d_in[1];
    const float* Wkv     = (const float*)d_in[2];
    const float* Wout    = (const float*)d_in[3];
    const float* bout    = (const float*)d_in[4];
    const float* rel_emb = (const float*)d_in[5];
    float* out = (float*)d_out;

    void *p;
    cudaGetSymbolAddress(&p, g_q);      float* qp  = (float*)p;
    cudaGetSymbolAddress(&p, g_kv);     float* kvp = (float*)p;
    cudaGetSymbolAddress(&p, g_ao);     float* aop = (float*)p;
    cudaGetSymbolAddress(&p, g_xh);     __nv_bfloat16* xh  = (__nv_bfloat16*)p;
    cudaGetSymbolAddress(&p, g_xl);     __nv_bfloat16* xl  = (__nv_bfloat16*)p;
    cudaGetSymbolAddress(&p, g_aoh);    __nv_bfloat16* aoh = (__nv_bfloat16*)p;
    cudaGetSymbolAddress(&p, g_aol);    __nv_bfloat16* aol = (__nv_bfloat16*)p;
    cudaGetSymbolAddress(&p, g_wqt_h);  __nv_bfloat16* wqh = (__nv_bfloat16*)p;
    cudaGetSymbolAddress(&p, g_wqt_l);  __nv_bfloat16* wql = (__nv_bfloat16*)p;
    cudaGetSymbolAddress(&p, g_wkvt_h); __nv_bfloat16* wkh = (__nv_bfloat16*)p;
    cudaGetSymbolAddress(&p, g_wkvt_l); __nv_bfloat16* wkl = (__nv_bfloat16*)p;
    cudaGetSymbolAddress(&p, g_wot_h);  __nv_bfloat16* woh = (__nv_bfloat16*)p;
    cudaGetSymbolAddress(&p, g_wot_l);  __nv_bfloat16* wol = (__nv_bfloat16*)p;

    cudaFuncSetAttribute(gemm_mma, cudaFuncAttributeMaxDynamicSharedMemorySize, GEMM_SMEM);
    cudaFuncSetAttribute(flash_mma, cudaFuncAttributeMaxDynamicSharedMemorySize, (int)sizeof(FSmem));

    dim3 tb(32, 8);
    transpose_split_kernel<<<dim3(INNER_/32, DIMM/32), tb>>>(Wq,   wqh, wql, DIMM, INNER_);
    transpose_split_kernel<<<dim3((2*DHD)/32, DIMM/32), tb>>>(Wkv, wkh, wkl, DIMM, 2*DHD);
    transpose_split_kernel<<<dim3(DIMM/32, INNER_/32), tb>>>(Wout, woh, wol, INNER_, DIMM);
    split_kernel<<<(ROWS*DIMM/4 + 255)/256, 256>>>(x, xh, xl, ROWS*DIMM/4);

    // q = x @ Wq
    gemm_mma<<<dim3(INNER_/128, ROWS/128), 256, GEMM_SMEM>>>(xh, xl, wqh, wql, qp, INNER_, nullptr);
    // kv = x @ Wkv
    gemm_mma<<<dim3(1, ROWS/128), 256, GEMM_SMEM>>>(xh, xl, wkh, wkl, kvp, 2*DHD, nullptr);
    // attention
    flash_mma<<<dim3(SEQ/64, HEADS, BATCH), 256, sizeof(FSmem)>>>(qp, kvp, rel_emb, aop);
    // out = ao @ Wout + bout
    split_kernel<<<(ROWS*INNER_/4 + 255)/256, 256>>>(aop, aoh, aol, ROWS*INNER_/4);
    gemm_mma<<<dim3(DIMM/128, ROWS/128), 256, GEMM_SMEM>>>(aoh, aol, woh, wol, out, DIMM, bout);
}

// round 5
// speedup vs baseline: 3.6162x; 1.5517x over previous
#include <cuda_runtime.h>
#include <cuda_bf16.h>
#include <math.h>
#include <stdint.h>

#define BATCH 2
#define SEQ   2048
#define DIMM  1024
#define HEADS 16
#define DHD   64
#define INNER_ (HEADS*DHD)      // 1024
#define ROWS  (BATCH*SEQ)       // 4096
#define KDIM  1024

// ---------------- scratch (no cudaMalloc allowed) ----------------
__device__ __align__(256) float g_kv[ROWS*2*DHD];                    // [row][k|v]
__device__ __align__(256) __nv_bfloat16 g_qh [ROWS*INNER_];
__device__ __align__(256) __nv_bfloat16 g_ql [ROWS*INNER_];
__device__ __align__(256) __nv_bfloat16 g_kh [BATCH*SEQ*DHD];
__device__ __align__(256) __nv_bfloat16 g_kl [BATCH*SEQ*DHD];
__device__ __align__(256) __nv_bfloat16 g_vth[BATCH*DHD*SEQ];        // transposed V
__device__ __align__(256) __nv_bfloat16 g_vtl[BATCH*DHD*SEQ];
__device__ __align__(256) __nv_bfloat16 g_aoh[ROWS*INNER_];
__device__ __align__(256) __nv_bfloat16 g_aol[ROWS*INNER_];
__device__ __align__(256) __nv_bfloat16 g_xh [ROWS*DIMM];
__device__ __align__(256) __nv_bfloat16 g_xl [ROWS*DIMM];
__device__ __align__(256) __nv_bfloat16 g_wcth[(INNER_+2*DHD)*DIMM]; // [Wq^T ; Wkv^T]
__device__ __align__(256) __nv_bfloat16 g_wctl[(INNER_+2*DHD)*DIMM];
__device__ __align__(256) __nv_bfloat16 g_woth[DIMM*INNER_];
__device__ __align__(256) __nv_bfloat16 g_wotl[DIMM*INNER_];

// ---------------- helpers ----------------
__device__ __forceinline__ uint32_t s2u(const void* p) {
    uint32_t a;
    asm("{ .reg .u64 t; cvta.to.shared.u64 t, %1; cvt.u32.u64 %0, t; }"
        : "=r"(a) : "l"(p));
    return a;
}
__device__ __forceinline__ void cp16(uint32_t dst, const void* src) {
    asm volatile("cp.async.cg.shared.global [%0], [%1], 16;" :: "r"(dst), "l"(src));
}
__device__ __forceinline__ void cp_commit() { asm volatile("cp.async.commit_group;" ::: "memory"); }

__device__ __forceinline__ void mma16816(float c[4], const uint32_t a[4], const uint32_t b[2]) {
    asm volatile("mma.sync.aligned.m16n8k16.row.col.f32.bf16.bf16.f32 "
        "{%0,%1,%2,%3}, {%4,%5,%6,%7}, {%8,%9}, {%0,%1,%2,%3};"
        : "+f"(c[0]), "+f"(c[1]), "+f"(c[2]), "+f"(c[3])
        : "r"(a[0]), "r"(a[1]), "r"(a[2]), "r"(a[3]), "r"(b[0]), "r"(b[1]));
}

// pack two floats into bf16x2 hi + bf16x2 lo (residual)
__device__ __forceinline__ void pack_hl(float a, float b, uint32_t& h, uint32_t& l) {
    __nv_bfloat16 ha = __float2bfloat16(a), hb = __float2bfloat16(b);
    __nv_bfloat16 la = __float2bfloat16(a - __bfloat162float(ha));
    __nv_bfloat16 lb = __float2bfloat16(b - __bfloat162float(hb));
    __nv_bfloat162 hh = __halves2bfloat162(ha, hb);
    __nv_bfloat162 ll = __halves2bfloat162(la, lb);
    h = *reinterpret_cast<uint32_t*>(&hh);
    l = *reinterpret_cast<uint32_t*>(&ll);
}

// l4 = lane>>2, c2 = (lane&3)*2 must be in scope.
#define LDA_FR(fr, arr, row0, kcol, STRIDE) do { \
    (fr)[0] = *(const uint32_t*)&(arr)[((row0) + l4    )*(STRIDE) + (kcol) + c2    ]; \
    (fr)[1] = *(const uint32_t*)&(arr)[((row0) + l4 + 8)*(STRIDE) + (kcol) + c2    ]; \
    (fr)[2] = *(const uint32_t*)&(arr)[((row0) + l4    )*(STRIDE) + (kcol) + c2 + 8]; \
    (fr)[3] = *(const uint32_t*)&(arr)[((row0) + l4 + 8)*(STRIDE) + (kcol) + c2 + 8]; \
} while(0)
#define LDB_FR(fr, arr, n0, kcol, STRIDE) do { \
    (fr)[0] = *(const uint32_t*)&(arr)[((n0) + l4)*(STRIDE) + (kcol) + c2    ]; \
    (fr)[1] = *(const uint32_t*)&(arr)[((n0) + l4)*(STRIDE) + (kcol) + c2 + 8]; \
} while(0)

// ---------------------------------------------------------------------------
// Prep kernels
// ---------------------------------------------------------------------------
__global__ __launch_bounds__(256) void split_kernel(
    const float* __restrict__ A, __nv_bfloat16* __restrict__ H,
    __nv_bfloat16* __restrict__ L, int n4)
{
    int i = blockIdx.x * blockDim.x + threadIdx.x;
    if (i >= n4) return;
    float4 a = ((const float4*)A)[i];
    uint32_t h01, l01, h23, l23;
    pack_hl(a.x, a.y, h01, l01);
    pack_hl(a.z, a.w, h23, l23);
    ((uint32_t*)H)[2*i]   = h01; ((uint32_t*)H)[2*i+1] = h23;
    ((uint32_t*)L)[2*i]   = l01; ((uint32_t*)L)[2*i+1] = l23;
}

__global__ __launch_bounds__(256) void transpose_split_kernel(
    const float* __restrict__ W, __nv_bfloat16* __restrict__ TH,
    __nv_bfloat16* __restrict__ TL, int K, int N, float scale)
{
    __shared__ float tile[32][33];
    const int tx = threadIdx.x, ty = threadIdx.y;     // block (32,8)
    const int n0 = blockIdx.x * 32, k0 = blockIdx.y * 32;
    #pragma unroll
    for (int i = 0; i < 4; i++)
        tile[ty + 8*i][tx] = W[(size_t)(k0 + ty + 8*i) * N + n0 + tx];
    __syncthreads();
    #pragma unroll
    for (int i = 0; i < 4; i++) {
        float a = tile[tx][ty + 8*i] * scale;
        __nv_bfloat16 h = __float2bfloat16(a);
        __nv_bfloat16 l = __float2bfloat16(a - __bfloat162float(h));
        size_t o = (size_t)(n0 + ty + 8*i) * K + k0 + tx;
        TH[o] = h; TL[o] = l;
    }
}

// split + transpose kv: g_kv [row][128] -> Kh/Kl [b][j][64], Vth/Vtl [b][d][SEQ]
__global__ __launch_bounds__(256) void kvsplit_kernel(
    const float* __restrict__ KVin,
    __nv_bfloat16* __restrict__ KH, __nv_bfloat16* __restrict__ KL,
    __nv_bfloat16* __restrict__ VTH, __nv_bfloat16* __restrict__ VTL)
{
    __shared__ float vt[64][65];
    const int b = blockIdx.y, j0 = blockIdx.x * 64;
    const int tid = threadIdx.x;
    const int j = tid >> 2, g = (tid & 3) * 16;
    const float* rp = KVin + (size_t)(b*SEQ + j0 + j) * (2*DHD);
    #pragma unroll
    for (int c = 0; c < 4; c++) {
        float4 kq = *(const float4*)(rp + g + c*4);
        uint32_t h01, l01, h23, l23;
        pack_hl(kq.x, kq.y, h01, l01);
        pack_hl(kq.z, kq.w, h23, l23);
        size_t ko = (size_t)(b*SEQ + j0 + j)*DHD + g + c*4;
        *(uint32_t*)(KH + ko) = h01; *(uint32_t*)(KH + ko + 2) = h23;
        *(uint32_t*)(KL + ko) = l01; *(uint32_t*)(KL + ko + 2) = l23;
        float4 vq = *(const float4*)(rp + DHD + g + c*4);
        vt[j][g + c*4 + 0] = vq.x; vt[j][g + c*4 + 1] = vq.y;
        vt[j][g + c*4 + 2] = vq.z; vt[j][g + c*4 + 3] = vq.w;
    }
    __syncthreads();
    const int d = tid >> 2, jg = (tid & 3) * 16;
    #pragma unroll
    for (int i = 0; i < 16; i += 2) {
        float a = vt[jg + i][d], bb = vt[jg + i + 1][d];
        uint32_t h, l; pack_hl(a, bb, h, l);
        size_t vo = (size_t)(b*DHD + d)*SEQ + j0 + jg + i;
        *(uint32_t*)(VTH + vo) = h;
        *(uint32_t*)(VTL + vo) = l;
    }
}

// ---------------------------------------------------------------------------
// HMMA GEMM: CTA 128x128, BK=32, 2-stage cp.async, 8 warps x 32x64.
// MODE 0: fp32 C + bias.  MODE 1: cols<1024 -> split bf16 (q), col>=1024 -> fp32 kv.
// ---------------------------------------------------------------------------
#define GBK 32
#define GNSTG (KDIM/GBK)
#define GSTRIDE 40
#define GMATB (128*GSTRIDE*2)
#define GSTGB (4*GMATB)
#define GEMM_SMEM (2*GSTGB)

template<int MODE>
__global__ __launch_bounds__(256) void gemm_mma(
    const __nv_bfloat16* __restrict__ Ah, const __nv_bfloat16* __restrict__ Al,
    const __nv_bfloat16* __restrict__ Bh, const __nv_bfloat16* __restrict__ Bl,
    float* __restrict__ C, const float* __restrict__ bias, int Ncols,
    __nv_bfloat16* __restrict__ CH, __nv_bfloat16* __restrict__ CL,
    float* __restrict__ C2)
{
    extern __shared__ __align__(16) char smem[];
    const uint32_t sbuf = s2u(smem);
    const int tid = threadIdx.x, wid = tid >> 5, lane = tid & 31;
    const int l4 = lane >> 2, c2 = (lane & 3) * 2;
    const int wm = wid & 3, wn = wid >> 2;
    const int bn = blockIdx.x, bm = blockIdx.y;

    const __nv_bfloat16* pA[2] = { Ah + (size_t)(bm*128)*KDIM, Al + (size_t)(bm*128)*KDIM };
    const __nv_bfloat16* pB[2] = { Bh + (size_t)(bn*128)*KDIM, Bl + (size_t)(bn*128)*KDIM };

    const int r0 = tid >> 2, kc = tid & 3;
    const int r1 = r0 + 64;

    float acc[2][8][4];
    #pragma unroll
    for (int i = 0; i < 2; i++)
        #pragma unroll
        for (int j = 0; j < 8; j++)
            #pragma unroll
            for (int e = 0; e < 4; e++) acc[i][j][e] = 0.f;

    #define G_LOAD(S) do { \
        const int _k0 = (S) * GBK; \
        const uint32_t stb = sbuf + ((S) & 1) * GSTGB; \
        _Pragma("unroll") \
        for (int m = 0; m < 2; m++) { \
            cp16(stb + m*GMATB     + r0*80 + kc*16, pA[m] + (size_t)r0*KDIM + _k0 + kc*8); \
            cp16(stb + m*GMATB     + r1*80 + kc*16, pA[m] + (size_t)r1*KDIM + _k0 + kc*8); \
            cp16(stb + (m+2)*GMATB + r0*80 + kc*16, pB[m] + (size_t)r0*KDIM + _k0 + kc*8); \
            cp16(stb + (m+2)*GMATB + r1*80 + kc*16, pB[m] + (size_t)r1*KDIM + _k0 + kc*8); \
        } \
    } while (0)

    G_LOAD(0); cp_commit();

    for (int s = 0; s < GNSTG; s++) {
        if (s + 1 < GNSTG) {
            G_LOAD(s + 1); cp_commit();
            asm volatile("cp.async.wait_group 1;" ::: "memory");
        } else {
            asm volatile("cp.async.wait_group 0;" ::: "memory");
        }
        __syncthreads();

        const __nv_bfloat16* base = (const __nv_bfloat16*)(smem + (s & 1) * GSTGB);
        const __nv_bfloat16* As_h = base;
        const __nv_bfloat16* As_l = base + 128*GSTRIDE;
        const __nv_bfloat16* Bs_h = base + 2*128*GSTRIDE;
        const __nv_bfloat16* Bs_l = base + 3*128*GSTRIDE;
        const int arow = wm*32, bcol = wn*64;

        #pragma unroll
        for (int k16 = 0; k16 < 2; k16++) {
            const int kcol = k16 * 16;
            uint32_t af[2][4], bf_[8][2];
            #pragma unroll
            for (int mt = 0; mt < 2; mt++) LDA_FR(af[mt], As_h, arow + mt*16, kcol, GSTRIDE);
            #pragma unroll
            for (int nt = 0; nt < 8; nt++) LDB_FR(bf_[nt], Bs_h, bcol + nt*8, kcol, GSTRIDE);
            #pragma unroll
            for (int mt = 0; mt < 2; mt++)
                #pragma unroll
                for (int nt = 0; nt < 8; nt++) mma16816(acc[mt][nt], af[mt], bf_[nt]);
            #pragma unroll
            for (int nt = 0; nt < 8; nt++) LDB_FR(bf_[nt], Bs_l, bcol + nt*8, kcol, GSTRIDE);
            #pragma unroll
            for (int mt = 0; mt < 2; mt++)
                #pragma unroll
                for (int nt = 0; nt < 8; nt++) mma16816(acc[mt][nt], af[mt], bf_[nt]);
            #pragma unroll
            for (int mt = 0; mt < 2; mt++) LDA_FR(af[mt], As_l, arow + mt*16, kcol, GSTRIDE);
            #pragma unroll
            for (int nt = 0; nt < 8; nt++) LDB_FR(bf_[nt], Bs_h, bcol + nt*8, kcol, GSTRIDE);
            #pragma unroll
            for (int mt = 0; mt < 2; mt++)
                #pragma unroll
                for (int nt = 0; nt < 8; nt++) mma16816(acc[mt][nt], af[mt], bf_[nt]);
        }
        __syncthreads();
    }
    #undef G_LOAD

    #pragma unroll
    for (int mt = 0; mt < 2; mt++) {
        const int rg0 = bm*128 + wm*32 + mt*16 + l4;
        #pragma unroll
        for (int nt = 0; nt < 8; nt++) {
            const int cg = bn*128 + wn*64 + nt*8 + c2;
            if (MODE == 0) {
                float b0 = bias ? bias[cg] : 0.f;
                float b1 = bias ? bias[cg+1] : 0.f;
                float2 v0 = { acc[mt][nt][0] + b0, acc[mt][nt][1] + b1 };
                float2 v1 = { acc[mt][nt][2] + b0, acc[mt][nt][3] + b1 };
                *(float2*)(C + (size_t)rg0*Ncols + cg)     = v0;
                *(float2*)(C + (size_t)(rg0+8)*Ncols + cg) = v1;
            } else {
                if (bn < 8) {
                    uint32_t h0, l0v, h1, l1v;
                    pack_hl(acc[mt][nt][0], acc[mt][nt][1], h0, l0v);
                    pack_hl(acc[mt][nt][2], acc[mt][nt][3], h1, l1v);
                    *(uint32_t*)(CH + (size_t)rg0*INNER_ + cg)     = h0;
                    *(uint32_t*)(CL + (size_t)rg0*INNER_ + cg)     = l0v;
                    *(uint32_t*)(CH + (size_t)(rg0+8)*INNER_ + cg) = h1;
                    *(uint32_t*)(CL + (size_t)(rg0+8)*INNER_ + cg) = l1v;
                } else {
                    const int cc = cg - 1024;
                    float2 v0 = { acc[mt][nt][0], acc[mt][nt][1] };
                    float2 v1 = { acc[mt][nt][2], acc[mt][nt][3] };
                    *(float2*)(C2 + (size_t)rg0*(2*DHD) + cc)     = v0;
                    *(float2*)(C2 + (size_t)(rg0+8)*(2*DHD) + cc) = v1;
                }
            }
        }
    }
}

// ---------------------------------------------------------------------------
// T5 relative-position bucket (mirrors jax fp32 math)
// ---------------------------------------------------------------------------
__device__ __forceinline__ int rel_bucket(int nn) {
    if (nn < 16) return nn;
    float t = logf((float)nn * (1.0f/16.0f)) / 2.0794415416798357f * 16.0f;
    int v = 16 + (int)t;
    return v < 31 ? v : 31;
}

// ---------------------------------------------------------------------------
// Flash attention v2: q-tile 128, warp-local softmax, register P, double-buffered KV.
// Grid (SEQ/128, HEADS, BATCH), 256 threads = 8 warps (warp w -> 16 rows).
// ---------------------------------------------------------------------------
#define FSTRIDE 72
#define FTILE   (64*FSTRIDE*2)     // 9216 bytes per bf16 tile
#define FKHO 0
#define FKLO (1*FTILE)
#define FVHO (2*FTILE)
#define FVLO (3*FTILE)
#define FSTG (4*FTILE)             // 36864 per stage
#define FBIAS (2*FSTG)             // 73728
#define FLASH_SMEM (FBIAS + 2048*4)  // 81920

__global__ __launch_bounds__(256) void flash2(
    const __nv_bfloat16* __restrict__ QH, const __nv_bfloat16* __restrict__ QL,
    const __nv_bfloat16* __restrict__ KH, const __nv_bfloat16* __restrict__ KL,
    const __nv_bfloat16* __restrict__ VTH, const __nv_bfloat16* __restrict__ VTL,
    const float* __restrict__ rel_emb,
    __nv_bfloat16* __restrict__ AOH, __nv_bfloat16* __restrict__ AOL)
{
    extern __shared__ __align__(16) char smem[];
    const uint32_t sb = s2u(smem);
    float* biasv = (float*)(smem + FBIAS);

    const int qtb = (SEQ/128 - 1) - blockIdx.x;     // heavy CTAs first
    const int h = blockIdx.y, b = blockIdx.z;
    const int tid = threadIdx.x, lane = tid & 31, w = tid >> 5;
    const int l4 = lane >> 2, c2 = (lane & 3) * 2;
    const int i0 = qtb * 128;
    const int wrow = i0 + w * 16;

    // bias table (once per CTA)
    for (int nn = tid; nn < 2048; nn += 256)
        biasv[nn] = rel_emb[rel_bucket(nn)*HEADS + h] * 8.0f;

    // Q fragments in registers (hi/lo), 16 rows x 64 dims per warp
    uint32_t qhf[4][4], qlf[4][4];
    {
        const size_t rb = (size_t)(b*SEQ + wrow + l4) * INNER_ + h*DHD;
        #pragma unroll
        for (int k16 = 0; k16 < 4; k16++) {
            const int c = k16*16 + c2;
            qhf[k16][0] = *(const uint32_t*)(QH + rb + c);
            qhf[k16][1] = *(const uint32_t*)(QH + rb + 8*INNER_ + c);
            qhf[k16][2] = *(const uint32_t*)(QH + rb + c + 8);
            qhf[k16][3] = *(const uint32_t*)(QH + rb + 8*INNER_ + c + 8);
            qlf[k16][0] = *(const uint32_t*)(QL + rb + c);
            qlf[k16][1] = *(const uint32_t*)(QL + rb + 8*INNER_ + c);
            qlf[k16][2] = *(const uint32_t*)(QL + rb + c + 8);
            qlf[k16][3] = *(const uint32_t*)(QL + rb + 8*INNER_ + c + 8);
        }
    }

    float o[8][4];
    #pragma unroll
    for (int nt = 0; nt < 8; nt++)
        #pragma unroll
        for (int e = 0; e < 4; e++) o[nt][e] = 0.f;
    float m0 = -INFINITY, m1 = -INFINITY, l0 = 0.f, l1 = 0.f;

    const int jmax = (i0 + 127) >> 6;
    const int iwmax = wrow + 15;

    // KV stage loader: 4 tiles x 64 rows x 8 chunks of 16B = 2048 cp16 / 256 thr
    #define LOADKV(JT, S) do { \
        const int _j0 = (JT) * 64; \
        const uint32_t _sb = sb + (uint32_t)(S) * FSTG; \
        _Pragma("unroll") \
        for (int q = 0; q < 2; q++) { \
            const int id = tid*2 + q; \
            const int r = id >> 3, cc = id & 7; \
            const uint32_t so = (uint32_t)(r*144 + cc*16); \
            const size_t ksrc = (size_t)(b*SEQ + _j0 + r)*DHD + cc*8; \
            const size_t vsrc = (size_t)(b*DHD + r)*SEQ + _j0 + cc*8; \
            cp16(_sb + FKHO + so, KH  + ksrc); \
            cp16(_sb + FKLO + so, KL  + ksrc); \
            cp16(_sb + FVHO + so, VTH + vsrc); \
            cp16(_sb + FVLO + so, VTL + vsrc); \
        } \
    } while (0)

    LOADKV(0, 0); cp_commit();

    for (int jt = 0; jt <= jmax; jt++) {
        if (jt < jmax) {
            LOADKV(jt + 1, (jt + 1) & 1); cp_commit();
            asm volatile("cp.async.wait_group 1;" ::: "memory");
        } else {
            asm volatile("cp.async.wait_group 0;" ::: "memory");
        }
        __syncthreads();

        const int j0 = jt * 64;
        if (j0 <= iwmax) {   // warp-uniform skip of fully-masked blocks
            const char* stg = smem + (jt & 1) * FSTG;
            const __nv_bfloat16* Khs = (const __nv_bfloat16*)(stg + FKHO);
            const __nv_bfloat16* Kls = (const __nv_bfloat16*)(stg + FKLO);
            const __nv_bfloat16* Vhs = (const __nv_bfloat16*)(stg + FVHO);
            const __nv_bfloat16* Vls = (const __nv_bfloat16*)(stg + FVLO);

            // ---- S = Q K^T ----
            float s[8][4];
            #pragma unroll
            for (int nt = 0; nt < 8; nt++)
                #pragma unroll
                for (int e = 0; e < 4; e++) s[nt][e] = 0.f;

            #pragma unroll
            for (int k16 = 0; k16 < 4; k16++) {
                const int kcol = k16 * 16;
                #pragma unroll
                for (int nt = 0; nt < 8; nt++) {
                    uint32_t bh[2], bl[2];
                    LDB_FR(bh, Khs, nt*8, kcol, FSTRIDE);
                    mma16816(s[nt], qhf[k16], bh);
                    LDB_FR(bl, Kls, nt*8, kcol, FSTRIDE);
                    mma16816(s[nt], qhf[k16], bl);
                    mma16816(s[nt], qlf[k16], bh);
                }
            }

            // ---- bias + causal mask ----
            const bool masked = (j0 + 63 > wrow);
            const int irow0 = wrow + l4;
            #pragma unroll
            for (int nt = 0; nt < 8; nt++) {
                #pragma unroll
                for (int e = 0; e < 4; e++) {
                    const int ri = irow0 + ((e >> 1) << 3);
                    const int cj = j0 + nt*8 + c2 + (e & 1);
                    const int nn = ri - cj;
                    if (masked && nn < 0) s[nt][e] = -INFINITY;
                    else                  s[nt][e] += biasv[nn];
                }
            }

            // ---- warp-local online softmax ----
            float mc0 = -INFINITY, mc1 = -INFINITY;
            #pragma unroll
            for (int nt = 0; nt < 8; nt++) {
                mc0 = fmaxf(mc0, fmaxf(s[nt][0], s[nt][1]));
                mc1 = fmaxf(mc1, fmaxf(s[nt][2], s[nt][3]));
            }
            mc0 = fmaxf(mc0, __shfl_xor_sync(0xffffffffu, mc0, 1));
            mc0 = fmaxf(mc0, __shfl_xor_sync(0xffffffffu, mc0, 2));
            mc1 = fmaxf(mc1, __shfl_xor_sync(0xffffffffu, mc1, 1));
            mc1 = fmaxf(mc1, __shfl_xor_sync(0xffffffffu, mc1, 2));
            const float mn0 = fmaxf(m0, mc0), mn1 = fmaxf(m1, mc1);
            const float sc0 = __expf(m0 - mn0), sc1 = __expf(m1 - mn1);
            m0 = mn0; m1 = mn1;

            float rs0 = 0.f, rs1 = 0.f;
            #pragma unroll
            for (int nt = 0; nt < 8; nt++) {
                s[nt][0] = __expf(s[nt][0] - mn0);
                s[nt][1] = __expf(s[nt][1] - mn0);
                s[nt][2] = __expf(s[nt][2] - mn1);
                s[nt][3] = __expf(s[nt][3] - mn1);
                rs0 += s[nt][0] + s[nt][1];
                rs1 += s[nt][2] + s[nt][3];
            }
            rs0 += __shfl_xor_sync(0xffffffffu, rs0, 1);
            rs0 += __shfl_xor_sync(0xffffffffu, rs0, 2);
            rs1 += __shfl_xor_sync(0xffffffffu, rs1, 1);
            rs1 += __shfl_xor_sync(0xffffffffu, rs1, 2);
            l0 = l0*sc0 + rs0;
            l1 = l1*sc1 + rs1;

            #pragma unroll
            for (int nt = 0; nt < 8; nt++) {
                o[nt][0] *= sc0; o[nt][1] *= sc0;
                o[nt][2] *= sc1; o[nt][3] *= sc1;
            }

            // ---- O += P V (P packed in registers, hi/lo) ----
            #pragma unroll
            for (int kk = 0; kk < 4; kk++) {
                uint32_t pah[4], pal[4];
                pack_hl(s[2*kk  ][0], s[2*kk  ][1], pah[0], pal[0]);
                pack_hl(s[2*kk  ][2], s[2*kk  ][3], pah[1], pal[1]);
                pack_hl(s[2*kk+1][0], s[2*kk+1][1], pah[2], pal[2]);
                pack_hl(s[2*kk+1][2], s[2*kk+1][3], pah[3], pal[3]);
                const int kcol = kk * 16;
                #pragma unroll
                for (int nt = 0; nt < 8; nt++) {
                    uint32_t bh[2], bl[2];
                    LDB_FR(bh, Vhs, nt*8, kcol, FSTRIDE);
                    mma16816(o[nt], pah, bh);
                    LDB_FR(bl, Vls, nt*8, kcol, FSTRIDE);
                    mma16816(o[nt], pah, bl);
                    mma16816(o[nt], pal, bh);
                }
            }
        }
        __syncthreads();
    }
    #undef LOADKV

    // ---- normalize + write split bf16 output ----
    {
        const float inv0 = 1.0f / l0, inv1 = 1.0f / l1;
        const size_t rb = (size_t)(b*SEQ + wrow + l4) * INNER_ + h*DHD;
        #pragma unroll
        for (int nt = 0; nt < 8; nt++) {
            const int col = nt*8 + c2;
            uint32_t ph, pl;
            pack_hl(o[nt][0]*inv0, o[nt][1]*inv0, ph, pl);
            *(uint32_t*)(AOH + rb + col) = ph;
            *(uint32_t*)(AOL + rb + col) = pl;
            pack_hl(o[nt][2]*inv1, o[nt][3]*inv1, ph, pl);
            *(uint32_t*)(AOH + rb + 8*INNER_ + col) = ph;
            *(uint32_t*)(AOL + rb + 8*INNER_ + col) = pl;
        }
    }
}

// ---------------------------------------------------------------------------
extern "C" void kernel_launch(void* const* d_in, const int* in_sizes, int n_in,
                              void* d_out, int out_size)
{
    const float* x       = (const float*)d_in[0];
    const float* Wq      = (const float*)d_in[1];
    const float* Wkv     = (const float*)d_in[2];
    const float* Wout    = (const float*)d_in[3];
    const float* bout    = (const float*)d_in[4];
    const float* rel_emb = (const float*)d_in[5];
    float* out = (float*)d_out;

    void* p;
    cudaGetSymbolAddress(&p, g_kv);   float* kvp = (float*)p;
    cudaGetSymbolAddress(&p, g_qh);   __nv_bfloat16* qh  = (__nv_bfloat16*)p;
    cudaGetSymbolAddress(&p, g_ql);   __nv_bfloat16* ql  = (__nv_bfloat16*)p;
    cudaGetSymbolAddress(&p, g_kh);   __nv_bfloat16* kh  = (__nv_bfloat16*)p;
    cudaGetSymbolAddress(&p, g_kl);   __nv_bfloat16* kl  = (__nv_bfloat16*)p;
    cudaGetSymbolAddress(&p, g_vth);  __nv_bfloat16* vth = (__nv_bfloat16*)p;
    cudaGetSymbolAddress(&p, g_vtl);  __nv_bfloat16* vtl = (__nv_bfloat16*)p;
    cudaGetSymbolAddress(&p, g_aoh);  __nv_bfloat16* aoh = (__nv_bfloat16*)p;
    cudaGetSymbolAddress(&p, g_aol);  __nv_bfloat16* aol = (__nv_bfloat16*)p;
    cudaGetSymbolAddress(&p, g_xh);   __nv_bfloat16* xh  = (__nv_bfloat16*)p;
    cudaGetSymbolAddress(&p, g_xl);   __nv_bfloat16* xl  = (__nv_bfloat16*)p;
    cudaGetSymbolAddress(&p, g_wcth); __nv_bfloat16* wch = (__nv_bfloat16*)p;
    cudaGetSymbolAddress(&p, g_wctl); __nv_bfloat16* wcl = (__nv_bfloat16*)p;
    cudaGetSymbolAddress(&p, g_woth); __nv_bfloat16* woh = (__nv_bfloat16*)p;
    cudaGetSymbolAddress(&p, g_wotl); __nv_bfloat16* wol = (__nv_bfloat16*)p;

    cudaFuncSetAttribute(gemm_mma<0>, cudaFuncAttributeMaxDynamicSharedMemorySize, GEMM_SMEM);
    cudaFuncSetAttribute(gemm_mma<1>, cudaFuncAttributeMaxDynamicSharedMemorySize, GEMM_SMEM);
    cudaFuncSetAttribute(flash2, cudaFuncAttributeMaxDynamicSharedMemorySize, FLASH_SMEM);

    dim3 tb(32, 8);
    // weight prep (Wq pre-scaled by dim_head^-0.5)
    transpose_split_kernel<<<dim3(INNER_/32, DIMM/32), tb>>>(Wq,  wch, wcl, DIMM, INNER_, 0.125f);
    transpose_split_kernel<<<dim3((2*DHD)/32, DIMM/32), tb>>>(Wkv, wch + (size_t)INNER_*DIMM,
                                                              wcl + (size_t)INNER_*DIMM, DIMM, 2*DHD, 1.0f);
    transpose_split_kernel<<<dim3(DIMM/32, INNER_/32), tb>>>(Wout, woh, wol, INNER_, DIMM, 1.0f);
    split_kernel<<<(ROWS*DIMM/4 + 255)/256, 256>>>(x, xh, xl, ROWS*DIMM/4);

    // fused q|kv projection: writes q as split bf16, kv as fp32
    gemm_mma<1><<<dim3(9, ROWS/128), 256, GEMM_SMEM>>>(xh, xl, wch, wcl,
                                                       nullptr, nullptr, 0, qh, ql, kvp);
    // kv -> split K + transposed split V
    kvsplit_kernel<<<dim3(SEQ/64, BATCH), 256>>>(kvp, kh, kl, vth, vtl);
    // attention (writes split bf16 output directly)
    flash2<<<dim3(SEQ/128, HEADS, BATCH), 256, FLASH_SMEM>>>(qh, ql, kh, kl, vth, vtl,
                                                             rel_emb, aoh, aol);
    // out = ao @ Wout + bout
    gemm_mma<0><<<dim3(DIMM/128, ROWS/128), 256, GEMM_SMEM>>>(aoh, aol, woh, wol,
                                                              out, bout, DIMM,
                                                              nullptr, nullptr, nullptr);
}